// round 2
// baseline (speedup 1.0000x reference)
#include <cuda_runtime.h>
#include <math.h>

#define BB 2
#define SS 2048
#define DD 2048
#define NH 32
#define NKV 8
#define HD 64
#define KVD (NKV*HD)   /* 512 */
#define BS (BB*SS)     /* 4096 */

// Scratch (no cudaMalloc allowed): ~84 MB total
__device__ float g_Q[BS*DD];
__device__ float g_K[BS*KVD];
__device__ float g_V[BS*KVD];
__device__ float g_A[BS*DD];

// Buffer selectors so kernel_launch never needs cudaGetSymbolAddress
// (keeps the capture call free of ALL runtime API usage).
#define BUF_Q 0
#define BUF_K 1
#define BUF_V 2
#define BUF_A 3

__device__ __forceinline__ float* buf_ptr(int sel) {
    switch (sel) {
        case BUF_Q: return g_Q;
        case BUF_K: return g_K;
        case BUF_V: return g_V;
        default:    return g_A;
    }
}

// ---------------------------------------------------------------------------
// SGEMM: C[M,N] = A[M,K] @ B[K,N], all row-major, fp32.
// 128x128 block tile, BK=16, 256 threads, 8x8 per-thread microtile.
// A and/or C may be internal scratch buffers (selected by asel/csel) or
// external pointers (sel < 0 -> use the given pointer).
// Requires M%128==0, N%128==0, K%16==0 (true for all calls here).
// ---------------------------------------------------------------------------
__global__ __launch_bounds__(256) void sgemm_kernel(const float* Aext, int asel,
                                                    const float* __restrict__ Bm,
                                                    float* Cext, int csel,
                                                    int M, int N, int K)
{
    const float* A = (asel >= 0) ? buf_ptr(asel) : Aext;
    float* C       = (csel >= 0) ? buf_ptr(csel) : Cext;

    __shared__ float As[16][132];   // transposed: As[k][m], padded vs bank conflicts
    __shared__ float Bs[16][128];

    const int bm = blockIdx.y * 128;
    const int bn = blockIdx.x * 128;
    const int tid = threadIdx.x;
    const int ty = tid >> 4;        // 0..15
    const int tx = tid & 15;        // 0..15

    float acc[8][8];
#pragma unroll
    for (int i = 0; i < 8; i++)
#pragma unroll
        for (int j = 0; j < 8; j++) acc[i][j] = 0.f;

    const int ar = tid >> 2;            // A tile row (0..63, +64)
    const int ac = (tid & 3) << 2;      // A tile col (float4)
    const int br = tid >> 5;            // B tile row (0..7, +8)
    const int bc = (tid & 31) << 2;     // B tile col (float4)

    for (int k0 = 0; k0 < K; k0 += 16) {
#pragma unroll
        for (int i = 0; i < 2; i++) {
            int r = ar + i * 64;
            float4 v = *(const float4*)(A + (size_t)(bm + r) * K + k0 + ac);
            As[ac + 0][r] = v.x; As[ac + 1][r] = v.y;
            As[ac + 2][r] = v.z; As[ac + 3][r] = v.w;
        }
#pragma unroll
        for (int i = 0; i < 2; i++) {
            int r = br + i * 8;
            *(float4*)&Bs[r][bc] = *(const float4*)(Bm + (size_t)(k0 + r) * N + bn + bc);
        }
        __syncthreads();
#pragma unroll
        for (int kk = 0; kk < 16; kk++) {
            float a[8], b[8];
#pragma unroll
            for (int i = 0; i < 8; i++) a[i] = As[kk][ty * 8 + i];
#pragma unroll
            for (int j = 0; j < 8; j++) b[j] = Bs[kk][tx * 8 + j];
#pragma unroll
            for (int i = 0; i < 8; i++)
#pragma unroll
                for (int j = 0; j < 8; j++)
                    acc[i][j] = fmaf(a[i], b[j], acc[i][j]);
        }
        __syncthreads();
    }

#pragma unroll
    for (int i = 0; i < 8; i++) {
        float* cp = C + (size_t)(bm + ty * 8 + i) * N + bn + tx * 8;
        *(float4*)cp       = make_float4(acc[i][0], acc[i][1], acc[i][2], acc[i][3]);
        *(float4*)(cp + 4) = make_float4(acc[i][4], acc[i][5], acc[i][6], acc[i][7]);
    }
}

// ---------------------------------------------------------------------------
// RoPE applied in-place to g_Q and g_K.
// Q pairs: idx = ((b*S+s)*NH + h)*32 + p  -> float2 at g_Q + 2*idx
// K pairs: j   = ((b*S+s)*NKV + h)*32 + p -> float2 at g_K + 2*j
// ---------------------------------------------------------------------------
__global__ void rope_kernel(const float* __restrict__ fcos, const float* __restrict__ fsin)
{
    const int NQP = BS * NH * (HD / 2);   // 4194304
    const int NKP = BS * NKV * (HD / 2);  // 1048576
    int idx = blockIdx.x * blockDim.x + threadIdx.x;
    if (idx < NQP) {
        int p = idx & 31;
        int srow = (idx >> 10) & (SS - 1);      // idx / (NH*32) mod S
        float c = fcos[srow * 32 + p];
        float sn = fsin[srow * 32 + p];
        float2 v = ((float2*)g_Q)[idx];
        ((float2*)g_Q)[idx] = make_float2(v.x * c - v.y * sn, v.x * sn + v.y * c);
    } else if (idx < NQP + NKP) {
        int j = idx - NQP;
        int p = j & 31;
        int srow = (j >> 8) & (SS - 1);         // j / (NKV*32) mod S
        float c = fcos[srow * 32 + p];
        float sn = fsin[srow * 32 + p];
        float2 v = ((float2*)g_K)[j];
        ((float2*)g_K)[j] = make_float2(v.x * c - v.y * sn, v.x * sn + v.y * c);
    }
}

// ---------------------------------------------------------------------------
// Causal flash attention, 64x64 tiles, fp32, online softmax.
// Grid: (S/64, NH, B). 256 threads.
// Thread owns row r = tid>>2; score cols j0..j0+15 and out dims d0..d0+15
// where j0 = d0 = (tid&3)*16. KP buffer is K^T during scores, P^T during PV.
// Static smem = 3 * 16 KB = 48 KB exactly.
// ---------------------------------------------------------------------------
__global__ __launch_bounds__(256) void attn_kernel()
{
    __shared__ float Qs[64 * 64];   // Qs[d*64 + r]  (transposed)
    __shared__ float KP[64 * 64];   // K: [d*64 + j] ; then P: [j*64 + r]
    __shared__ float Vs[64 * 64];   // [j*64 + d]

    const int qt = blockIdx.x;
    const int h  = blockIdx.y;
    const int b  = blockIdx.z;
    const int hk = h >> 2;          // NREP = 4
    const int tid = threadIdx.x;
    const int r  = tid >> 2;        // 0..63
    const int c4 = tid & 3;
    const int j0 = c4 * 16;
    const int d0 = c4 * 16;
    const int q0 = qt * 64;

    // Load Q tile transposed
#pragma unroll
    for (int it = 0; it < 4; it++) {
        int lin = tid + it * 256;           // float4 index, 0..1023
        int rr = lin >> 4;
        int dd = (lin & 15) << 2;
        float4 v = *(const float4*)(g_Q + (size_t)(b * SS + q0 + rr) * DD + h * HD + dd);
        Qs[(dd + 0) * 64 + rr] = v.x; Qs[(dd + 1) * 64 + rr] = v.y;
        Qs[(dd + 2) * 64 + rr] = v.z; Qs[(dd + 3) * 64 + rr] = v.w;
    }

    float acc[16];
#pragma unroll
    for (int i = 0; i < 16; i++) acc[i] = 0.f;
    float m = -INFINITY, l = 0.f;

    for (int kt = 0; kt <= qt; kt++) {
        __syncthreads();   // prior iter done with KP/Vs (also orders Q stores on iter 0)
#pragma unroll
        for (int it = 0; it < 4; it++) {
            int lin = tid + it * 256;
            int jj = lin >> 4;
            int dd = (lin & 15) << 2;
            float4 kv = *(const float4*)(g_K + (size_t)(b * SS + kt * 64 + jj) * KVD + hk * HD + dd);
            KP[(dd + 0) * 64 + jj] = kv.x; KP[(dd + 1) * 64 + jj] = kv.y;
            KP[(dd + 2) * 64 + jj] = kv.z; KP[(dd + 3) * 64 + jj] = kv.w;
            float4 vv = *(const float4*)(g_V + (size_t)(b * SS + kt * 64 + jj) * KVD + hk * HD + dd);
            *(float4*)&Vs[jj * 64 + dd] = vv;
        }
        __syncthreads();

        // S = Q K^T
        float s[16];
#pragma unroll
        for (int i = 0; i < 16; i++) s[i] = 0.f;
#pragma unroll 8
        for (int d = 0; d < 64; d++) {
            float qv = Qs[d * 64 + r];
#pragma unroll
            for (int i = 0; i < 16; i++)
                s[i] = fmaf(qv, KP[d * 64 + j0 + i], s[i]);
        }
        const float scale = 0.125f;   // 1/sqrt(64)
        if (kt == qt) {
#pragma unroll
            for (int i = 0; i < 16; i++)
                s[i] = (j0 + i <= r) ? s[i] * scale : -INFINITY;
        } else {
#pragma unroll
            for (int i = 0; i < 16; i++) s[i] *= scale;
        }

        // Online softmax (row split over 4 threads -> quad shfl reduce)
        float mt = s[0];
#pragma unroll
        for (int i = 1; i < 16; i++) mt = fmaxf(mt, s[i]);
        mt = fmaxf(mt, __shfl_xor_sync(0xffffffffu, mt, 1));
        mt = fmaxf(mt, __shfl_xor_sync(0xffffffffu, mt, 2));
        float m_new = fmaxf(m, mt);
        float corr = __expf(m - m_new);
        float lt = 0.f;
#pragma unroll
        for (int i = 0; i < 16; i++) {
            s[i] = __expf(s[i] - m_new);
            lt += s[i];
        }
        lt += __shfl_xor_sync(0xffffffffu, lt, 1);
        lt += __shfl_xor_sync(0xffffffffu, lt, 2);
        l = l * corr + lt;
        m = m_new;
#pragma unroll
        for (int i = 0; i < 16; i++) acc[i] *= corr;

        __syncthreads();   // everyone done reading KP as K
#pragma unroll
        for (int i = 0; i < 16; i++)
            KP[(j0 + i) * 64 + r] = s[i];   // store P transposed
        __syncthreads();

        // O += P V
#pragma unroll 8
        for (int j = 0; j < 64; j++) {
            float pv = KP[j * 64 + r];
#pragma unroll
            for (int i = 0; i < 16; i++)
                acc[i] = fmaf(pv, Vs[j * 64 + d0 + i], acc[i]);
        }
    }

    float inv = 1.0f / l;
    float* op = g_A + (size_t)(b * SS + q0 + r) * DD + h * HD + d0;
#pragma unroll
    for (int i = 0; i < 16; i += 4)
        *(float4*)(op + i) = make_float4(acc[i] * inv, acc[i + 1] * inv,
                                         acc[i + 2] * inv, acc[i + 3] * inv);
}

// ---------------------------------------------------------------------------
extern "C" void kernel_launch(void* const* d_in, const int* in_sizes, int n_in,
                              void* d_out, int out_size)
{
    const float* x   = (const float*)d_in[0];
    const float* fco = (const float*)d_in[1];
    const float* fsi = (const float*)d_in[2];
    const float* wq  = (const float*)d_in[3];
    const float* wk  = (const float*)d_in[4];
    const float* wv  = (const float*)d_in[5];
    const float* wo  = (const float*)d_in[6];
    float* out = (float*)d_out;

    // Projections (write into internal scratch via selector, no symbol lookup)
    sgemm_kernel<<<dim3(DD / 128, BS / 128), 256>>>(x, -1, wq, nullptr, BUF_Q, BS, DD, DD);
    sgemm_kernel<<<dim3(KVD / 128, BS / 128), 256>>>(x, -1, wk, nullptr, BUF_K, BS, KVD, DD);
    sgemm_kernel<<<dim3(KVD / 128, BS / 128), 256>>>(x, -1, wv, nullptr, BUF_V, BS, KVD, DD);

    // RoPE on Q and K
    {
        int total = BS * NH * (HD / 2) + BS * NKV * (HD / 2);
        rope_kernel<<<(total + 255) / 256, 256>>>(fco, fsi);
    }

    // Causal flash attention
    attn_kernel<<<dim3(SS / 64, NH, BB), 256>>>();

    // Output projection (read scratch A, write external out)
    sgemm_kernel<<<dim3(DD / 128, BS / 128), 256>>>(nullptr, BUF_A, wo, out, -1, BS, DD, DD);
}

// round 3
// speedup vs baseline: 2.7887x; 2.7887x over previous
#include <cuda_runtime.h>
#include <cuda_bf16.h>
#include <math.h>

#define BB 2
#define SS 2048
#define DD 2048
#define NH 32
#define NKV 8
#define HD 64
#define KVD (NKV*HD)   /* 512 */
#define BS (BB*SS)     /* 4096 */

// fp32 scratch
__device__ float g_Q[BS*DD];
__device__ float g_K[BS*KVD];
__device__ float g_V[BS*KVD];
__device__ float g_A[BS*DD];

// bf16 hi/lo split scratch
__device__ __nv_bfloat16 g_xh[BS*DD],  g_xl[BS*DD];
__device__ __nv_bfloat16 g_Ah[BS*DD],  g_Al[BS*DD];
__device__ __nv_bfloat16 g_wqh[DD*DD], g_wql[DD*DD];
__device__ __nv_bfloat16 g_wkh[DD*KVD],g_wkl[DD*KVD];
__device__ __nv_bfloat16 g_wvh[DD*KVD],g_wvl[DD*KVD];
__device__ __nv_bfloat16 g_woh[DD*DD], g_wol[DD*DD];

// ---------------------------------------------------------------------------
// fp32 -> (hi, lo) bf16 split.  dsel: 0=x 1=wq 2=wk 3=wv 4=wo 5=A(from g_A)
// ---------------------------------------------------------------------------
__global__ void cvt_kernel(const float* srcExt, int srcIsA, int dsel, int n)
{
    int i = blockIdx.x * blockDim.x + threadIdx.x;
    if (i >= n) return;
    const float* src = srcIsA ? g_A : srcExt;
    float v = src[i];
    __nv_bfloat16 hi = __float2bfloat16(v);
    __nv_bfloat16 lo = __float2bfloat16(v - __bfloat162float(hi));
    __nv_bfloat16 *ph, *pl;
    switch (dsel) {
        case 0: ph = g_xh;  pl = g_xl;  break;
        case 1: ph = g_wqh; pl = g_wql; break;
        case 2: ph = g_wkh; pl = g_wkl; break;
        case 3: ph = g_wvh; pl = g_wvl; break;
        case 4: ph = g_woh; pl = g_wol; break;
        default:ph = g_Ah;  pl = g_Al;  break;
    }
    ph[i] = hi; pl[i] = lo;
}

// ---------------------------------------------------------------------------
// bf16-split GEMM: C = A @ B, fp32 result, via 3x mma.sync.m16n8k16.bf16
//   C = Ah*Bh + Ah*Bl + Al*Bh   (fp32 accumulate)
// 128x128 block tile, BK=32, 256 threads (8 warps as 2x4, warp tile 64x32).
// ---------------------------------------------------------------------------
__device__ __forceinline__ void mma_bf16(float* c, const unsigned* a, const unsigned* b)
{
    asm volatile(
        "mma.sync.aligned.m16n8k16.row.col.f32.bf16.bf16.f32 "
        "{%0,%1,%2,%3}, {%4,%5,%6,%7}, {%8,%9}, {%0,%1,%2,%3};\n"
        : "+f"(c[0]), "+f"(c[1]), "+f"(c[2]), "+f"(c[3])
        : "r"(a[0]), "r"(a[1]), "r"(a[2]), "r"(a[3]), "r"(b[0]), "r"(b[1]));
}

__device__ __forceinline__ unsigned pack2(const __nv_bfloat16* p0, const __nv_bfloat16* p1)
{
    unsigned u0 = *(const unsigned short*)p0;
    unsigned u1 = *(const unsigned short*)p1;
    return u0 | (u1 << 16);
}

__global__ __launch_bounds__(256) void gemm_bf16split(int asel, int bsel,
                                                      float* Cext, int csel,
                                                      int M, int N, int K)
{
    const __nv_bfloat16 *Ah, *Al, *Bh, *Bl;
    if (asel == 0) { Ah = g_xh; Al = g_xl; } else { Ah = g_Ah; Al = g_Al; }
    switch (bsel) {
        case 0:  Bh = g_wqh; Bl = g_wql; break;
        case 1:  Bh = g_wkh; Bl = g_wkl; break;
        case 2:  Bh = g_wvh; Bl = g_wvl; break;
        default: Bh = g_woh; Bl = g_wol; break;
    }
    float* C = (csel == 0) ? g_Q : (csel == 1) ? g_K : (csel == 2) ? g_V : Cext;

    __shared__ __nv_bfloat16 Ash[2][128][40];    // [hi/lo][m][k], pad 40: frag loads conflict-free
    __shared__ __nv_bfloat16 Bsh[2][32][136];    // [hi/lo][k][n], row-major, pad 136

    const int tid  = threadIdx.x;
    const int lane = tid & 31;
    const int wid  = tid >> 5;
    const int g    = lane >> 2;      // 0..7
    const int tg   = lane & 3;       // 0..3
    const int warpM = (wid >> 2) * 64;   // 0 or 64
    const int warpN = (wid & 3) * 32;    // 0..96
    const int bm = blockIdx.y * 128;
    const int bn = blockIdx.x * 128;

    float acc[4][4][4];
#pragma unroll
    for (int a = 0; a < 4; a++)
#pragma unroll
        for (int b = 0; b < 4; b++)
#pragma unroll
            for (int c = 0; c < 4; c++) acc[a][b][c] = 0.f;

    const __nv_bfloat16* Aarr[2] = {Ah, Al};
    const __nv_bfloat16* Barr[2] = {Bh, Bl};

    uint4 pa[2][2], pb[2][2];

    // fetch kblock kb into prefetch regs
    auto fetch = [&](int kb) {
        const int k0 = kb * 32;
#pragma unroll
        for (int h = 0; h < 2; h++)
#pragma unroll
            for (int i = 0; i < 2; i++) {
                int q  = tid + i * 256;
                int ar = q >> 2, ak = (q & 3) * 8;
                pa[h][i] = *(const uint4*)(Aarr[h] + (size_t)(bm + ar) * K + k0 + ak);
                int bk = q >> 4, bnc = (q & 15) * 8;
                pb[h][i] = *(const uint4*)(Barr[h] + (size_t)(k0 + bk) * N + bn + bnc);
            }
    };
    auto stores = [&]() {
#pragma unroll
        for (int h = 0; h < 2; h++)
#pragma unroll
            for (int i = 0; i < 2; i++) {
                int q  = tid + i * 256;
                int ar = q >> 2, ak = (q & 3) * 8;
                *(uint2*)&Ash[h][ar][ak]     = make_uint2(pa[h][i].x, pa[h][i].y);
                *(uint2*)&Ash[h][ar][ak + 4] = make_uint2(pa[h][i].z, pa[h][i].w);
                int bk = q >> 4, bnc = (q & 15) * 8;
                *(uint4*)&Bsh[h][bk][bnc] = pb[h][i];
            }
    };

    fetch(0);
    const int nkb = K / 32;
    for (int kb = 0; kb < nkb; kb++) {
        __syncthreads();
        stores();
        if (kb + 1 < nkb) fetch(kb + 1);
        __syncthreads();

#pragma unroll
        for (int kk = 0; kk < 2; kk++) {
            const int kA = kk * 16 + tg * 2;
            unsigned ah[4][4], al2[4][4];
#pragma unroll
            for (int mt = 0; mt < 4; mt++) {
                int r0 = warpM + mt * 16 + g;
                ah[mt][0]  = *(const unsigned*)&Ash[0][r0][kA];
                ah[mt][1]  = *(const unsigned*)&Ash[0][r0 + 8][kA];
                ah[mt][2]  = *(const unsigned*)&Ash[0][r0][kA + 8];
                ah[mt][3]  = *(const unsigned*)&Ash[0][r0 + 8][kA + 8];
                al2[mt][0] = *(const unsigned*)&Ash[1][r0][kA];
                al2[mt][1] = *(const unsigned*)&Ash[1][r0 + 8][kA];
                al2[mt][2] = *(const unsigned*)&Ash[1][r0][kA + 8];
                al2[mt][3] = *(const unsigned*)&Ash[1][r0 + 8][kA + 8];
            }
            unsigned bh[4][2], bl2[4][2];
#pragma unroll
            for (int nt = 0; nt < 4; nt++) {
                int c0 = warpN + nt * 8 + g;
                bh[nt][0]  = pack2(&Bsh[0][kA][c0],     &Bsh[0][kA + 1][c0]);
                bh[nt][1]  = pack2(&Bsh[0][kA + 8][c0], &Bsh[0][kA + 9][c0]);
                bl2[nt][0] = pack2(&Bsh[1][kA][c0],     &Bsh[1][kA + 1][c0]);
                bl2[nt][1] = pack2(&Bsh[1][kA + 8][c0], &Bsh[1][kA + 9][c0]);
            }
#pragma unroll
            for (int mt = 0; mt < 4; mt++)
#pragma unroll
                for (int nt = 0; nt < 4; nt++) {
                    mma_bf16(acc[mt][nt], ah[mt],  bh[nt]);
                    mma_bf16(acc[mt][nt], ah[mt],  bl2[nt]);
                    mma_bf16(acc[mt][nt], al2[mt], bh[nt]);
                }
        }
    }

#pragma unroll
    for (int mt = 0; mt < 4; mt++)
#pragma unroll
        for (int nt = 0; nt < 4; nt++) {
            int row = bm + warpM + mt * 16 + g;
            int col = bn + warpN + nt * 8 + tg * 2;
            *(float2*)&C[(size_t)row * N + col] =
                make_float2(acc[mt][nt][0], acc[mt][nt][1]);
            *(float2*)&C[(size_t)(row + 8) * N + col] =
                make_float2(acc[mt][nt][2], acc[mt][nt][3]);
        }
}

// ---------------------------------------------------------------------------
// RoPE in-place on g_Q, g_K (unchanged from passing baseline)
// ---------------------------------------------------------------------------
__global__ void rope_kernel(const float* __restrict__ fcos, const float* __restrict__ fsin)
{
    const int NQP = BS * NH * (HD / 2);
    const int NKP = BS * NKV * (HD / 2);
    int idx = blockIdx.x * blockDim.x + threadIdx.x;
    if (idx < NQP) {
        int p = idx & 31;
        int srow = (idx >> 10) & (SS - 1);
        float c = fcos[srow * 32 + p];
        float sn = fsin[srow * 32 + p];
        float2 v = ((float2*)g_Q)[idx];
        ((float2*)g_Q)[idx] = make_float2(v.x * c - v.y * sn, v.x * sn + v.y * c);
    } else if (idx < NQP + NKP) {
        int j = idx - NQP;
        int p = j & 31;
        int srow = (j >> 8) & (SS - 1);
        float c = fcos[srow * 32 + p];
        float sn = fsin[srow * 32 + p];
        float2 v = ((float2*)g_K)[j];
        ((float2*)g_K)[j] = make_float2(v.x * c - v.y * sn, v.x * sn + v.y * c);
    }
}

// ---------------------------------------------------------------------------
// Causal flash attention, 64x64 tiles, fp32, 4x4 microtiles (16x16 threads).
// All smem traffic is float4; transposed stores use XOR swizzle (4-way max).
// ---------------------------------------------------------------------------
__device__ __forceinline__ int swzi(int a, int b) {   // scalar element (a=major, b=minor)
    return a * 64 + (((b & 60) ^ ((a & 15) << 2)) | (b & 3));
}
__device__ __forceinline__ int swz4(int a, int b4) {  // float4 base (b4 multiple of 4)
    return a * 64 + (b4 ^ ((a & 15) << 2));
}

__global__ __launch_bounds__(256) void attn_kernel()
{
    __shared__ float Qs[64 * 64];   // [d][r] swizzled
    __shared__ float KP[64 * 64];   // K phase: [d][j] swizzled ; P phase: [j][r] swizzled
    __shared__ float Vs[64 * 64];   // [j][d] plain

    const int qt = blockIdx.x;
    const int h  = blockIdx.y;
    const int b  = blockIdx.z;
    const int hk = h >> 2;
    const int tid = threadIdx.x;
    const int tx = tid & 15, ty = tid >> 4;
    const int tx4 = tx * 4, ty4 = ty * 4;
    const int q0 = qt * 64;

    // Q tile, transposed + swizzled
#pragma unroll
    for (int it = 0; it < 4; it++) {
        int lin = tid + it * 256;
        int rr = lin >> 4;
        int dd = (lin & 15) << 2;
        float4 v = *(const float4*)(g_Q + (size_t)(b * SS + q0 + rr) * DD + h * HD + dd);
        Qs[swzi(dd + 0, rr)] = v.x; Qs[swzi(dd + 1, rr)] = v.y;
        Qs[swzi(dd + 2, rr)] = v.z; Qs[swzi(dd + 3, rr)] = v.w;
    }

    float m_[4], l_[4], acc[4][4];
#pragma unroll
    for (int i = 0; i < 4; i++) {
        m_[i] = -INFINITY; l_[i] = 0.f;
#pragma unroll
        for (int j = 0; j < 4; j++) acc[i][j] = 0.f;
    }

    for (int kt = 0; kt <= qt; kt++) {
        __syncthreads();   // prior iter done with KP/Vs (covers Q stores on iter 0)
#pragma unroll
        for (int it = 0; it < 4; it++) {
            int lin = tid + it * 256;
            int jj = lin >> 4;
            int dd = (lin & 15) << 2;
            size_t base = (size_t)(b * SS + kt * 64 + jj) * KVD + hk * HD + dd;
            float4 kv = *(const float4*)(g_K + base);
            KP[swzi(dd + 0, jj)] = kv.x; KP[swzi(dd + 1, jj)] = kv.y;
            KP[swzi(dd + 2, jj)] = kv.z; KP[swzi(dd + 3, jj)] = kv.w;
            float4 vv = *(const float4*)(g_V + base);
            *(float4*)&Vs[jj * 64 + dd] = vv;
        }
        __syncthreads();

        // S = Q K^T  (4x4 per thread)
        float s[4][4];
#pragma unroll
        for (int i = 0; i < 4; i++)
#pragma unroll
            for (int j = 0; j < 4; j++) s[i][j] = 0.f;
#pragma unroll 8
        for (int d = 0; d < 64; d++) {
            float4 av = *(const float4*)&Qs[swz4(d, ty4)];
            float4 bv = *(const float4*)&KP[swz4(d, tx4)];
            float a0 = av.x, a1 = av.y, a2 = av.z, a3 = av.w;
            float b0 = bv.x, b1 = bv.y, b2 = bv.z, b3 = bv.w;
            s[0][0] = fmaf(a0, b0, s[0][0]); s[0][1] = fmaf(a0, b1, s[0][1]);
            s[0][2] = fmaf(a0, b2, s[0][2]); s[0][3] = fmaf(a0, b3, s[0][3]);
            s[1][0] = fmaf(a1, b0, s[1][0]); s[1][1] = fmaf(a1, b1, s[1][1]);
            s[1][2] = fmaf(a1, b2, s[1][2]); s[1][3] = fmaf(a1, b3, s[1][3]);
            s[2][0] = fmaf(a2, b0, s[2][0]); s[2][1] = fmaf(a2, b1, s[2][1]);
            s[2][2] = fmaf(a2, b2, s[2][2]); s[2][3] = fmaf(a2, b3, s[2][3]);
            s[3][0] = fmaf(a3, b0, s[3][0]); s[3][1] = fmaf(a3, b1, s[3][1]);
            s[3][2] = fmaf(a3, b2, s[3][2]); s[3][3] = fmaf(a3, b3, s[3][3]);
        }

        const float scale = 0.125f;   // 1/sqrt(64)
        if (kt == qt) {
#pragma unroll
            for (int i = 0; i < 4; i++)
#pragma unroll
                for (int j = 0; j < 4; j++)
                    s[i][j] = (tx4 + j <= ty4 + i) ? s[i][j] * scale : -INFINITY;
        } else {
#pragma unroll
            for (int i = 0; i < 4; i++)
#pragma unroll
                for (int j = 0; j < 4; j++) s[i][j] *= scale;
        }

        // online softmax per row (reduce across 16 tx lanes)
#pragma unroll
        for (int i = 0; i < 4; i++) {
            float mt = fmaxf(fmaxf(s[i][0], s[i][1]), fmaxf(s[i][2], s[i][3]));
            mt = fmaxf(mt, __shfl_xor_sync(0xffffffffu, mt, 1));
            mt = fmaxf(mt, __shfl_xor_sync(0xffffffffu, mt, 2));
            mt = fmaxf(mt, __shfl_xor_sync(0xffffffffu, mt, 4));
            mt = fmaxf(mt, __shfl_xor_sync(0xffffffffu, mt, 8));
            float mn = fmaxf(m_[i], mt);
            float corr = __expf(m_[i] - mn);
            float lt = 0.f;
#pragma unroll
            for (int j = 0; j < 4; j++) {
                s[i][j] = __expf(s[i][j] - mn);
                lt += s[i][j];
            }
            lt += __shfl_xor_sync(0xffffffffu, lt, 1);
            lt += __shfl_xor_sync(0xffffffffu, lt, 2);
            lt += __shfl_xor_sync(0xffffffffu, lt, 4);
            lt += __shfl_xor_sync(0xffffffffu, lt, 8);
            l_[i] = l_[i] * corr + lt;
            m_[i] = mn;
#pragma unroll
            for (int j = 0; j < 4; j++) acc[i][j] *= corr;
        }

        __syncthreads();   // all threads done reading KP as K
#pragma unroll
        for (int j = 0; j < 4; j++) {
            int jc = tx4 + j;
            *(float4*)&KP[swz4(jc, ty4)] =
                make_float4(s[0][j], s[1][j], s[2][j], s[3][j]);   // P^T [j][r]
        }
        __syncthreads();

        // O += P V
#pragma unroll 8
        for (int j = 0; j < 64; j++) {
            float4 pv = *(const float4*)&KP[swz4(j, ty4)];
            float4 vv = *(const float4*)&Vs[j * 64 + tx4];
            float p0 = pv.x, p1 = pv.y, p2 = pv.z, p3 = pv.w;
            float v0 = vv.x, v1 = vv.y, v2 = vv.z, v3 = vv.w;
            acc[0][0] = fmaf(p0, v0, acc[0][0]); acc[0][1] = fmaf(p0, v1, acc[0][1]);
            acc[0][2] = fmaf(p0, v2, acc[0][2]); acc[0][3] = fmaf(p0, v3, acc[0][3]);
            acc[1][0] = fmaf(p1, v0, acc[1][0]); acc[1][1] = fmaf(p1, v1, acc[1][1]);
            acc[1][2] = fmaf(p1, v2, acc[1][2]); acc[1][3] = fmaf(p1, v3, acc[1][3]);
            acc[2][0] = fmaf(p2, v0, acc[2][0]); acc[2][1] = fmaf(p2, v1, acc[2][1]);
            acc[2][2] = fmaf(p2, v2, acc[2][2]); acc[2][3] = fmaf(p2, v3, acc[2][3]);
            acc[3][0] = fmaf(p3, v0, acc[3][0]); acc[3][1] = fmaf(p3, v1, acc[3][1]);
            acc[3][2] = fmaf(p3, v2, acc[3][2]); acc[3][3] = fmaf(p3, v3, acc[3][3]);
        }
    }

#pragma unroll
    for (int i = 0; i < 4; i++) {
        float inv = 1.0f / l_[i];
        *(float4*)&g_A[(size_t)(b * SS + q0 + ty4 + i) * DD + h * HD + tx4] =
            make_float4(acc[i][0] * inv, acc[i][1] * inv,
                        acc[i][2] * inv, acc[i][3] * inv);
    }
}

// ---------------------------------------------------------------------------
extern "C" void kernel_launch(void* const* d_in, const int* in_sizes, int n_in,
                              void* d_out, int out_size)
{
    const float* x   = (const float*)d_in[0];
    const float* fco = (const float*)d_in[1];
    const float* fsi = (const float*)d_in[2];
    const float* wq  = (const float*)d_in[3];
    const float* wk  = (const float*)d_in[4];
    const float* wv  = (const float*)d_in[5];
    const float* wo  = (const float*)d_in[6];
    float* out = (float*)d_out;

    // split-convert inputs to bf16 hi/lo
    cvt_kernel<<<(BS * DD + 255) / 256, 256>>>(x, 0, 0, BS * DD);
    cvt_kernel<<<(DD * DD + 255) / 256, 256>>>(wq, 0, 1, DD * DD);
    cvt_kernel<<<(DD * KVD + 255) / 256, 256>>>(wk, 0, 2, DD * KVD);
    cvt_kernel<<<(DD * KVD + 255) / 256, 256>>>(wv, 0, 3, DD * KVD);
    cvt_kernel<<<(DD * DD + 255) / 256, 256>>>(wo, 0, 4, DD * DD);

    // projections (tensor core, bf16-split)
    gemm_bf16split<<<dim3(DD / 128, BS / 128), 256>>>(0, 0, nullptr, 0, BS, DD, DD);
    gemm_bf16split<<<dim3(KVD / 128, BS / 128), 256>>>(0, 1, nullptr, 1, BS, KVD, DD);
    gemm_bf16split<<<dim3(KVD / 128, BS / 128), 256>>>(0, 2, nullptr, 2, BS, KVD, DD);

    // RoPE
    {
        int total = BS * NH * (HD / 2) + BS * NKV * (HD / 2);
        rope_kernel<<<(total + 255) / 256, 256>>>(fco, fsi);
    }

    // attention
    attn_kernel<<<dim3(SS / 64, NH, BB), 256>>>();

    // output projection
    cvt_kernel<<<(BS * DD + 255) / 256, 256>>>(nullptr, 1, 5, BS * DD);
    gemm_bf16split<<<dim3(DD / 128, BS / 128), 256>>>(1, 3, out, -1, BS, DD, DD);
}

// round 4
// speedup vs baseline: 4.8092x; 1.7245x over previous
#include <cuda_runtime.h>
#include <cuda_bf16.h>
#include <math.h>

#define BB 2
#define SS 2048
#define DD 2048
#define NH 32
#define NKV 8
#define HD 64
#define KVD (NKV*HD)   /* 512 */
#define BS (BB*SS)     /* 4096 */

// fp32 scratch (GEMM outputs)
__device__ float g_Q[BS*DD];
__device__ float g_K[BS*KVD];
__device__ float g_V[BS*KVD];

// bf16 hi/lo split scratch
__device__ __nv_bfloat16 g_xh[BS*DD],  g_xl[BS*DD];
__device__ __nv_bfloat16 g_Ah[BS*DD],  g_Al[BS*DD];
__device__ __nv_bfloat16 g_Qh[BS*DD],  g_Ql[BS*DD];
__device__ __nv_bfloat16 g_Kh[BS*KVD], g_Kl[BS*KVD];
__device__ __nv_bfloat16 g_Vh[BS*KVD], g_Vl[BS*KVD];
__device__ __nv_bfloat16 g_wqh[DD*DD], g_wql[DD*DD];
__device__ __nv_bfloat16 g_wkh[DD*KVD],g_wkl[DD*KVD];
__device__ __nv_bfloat16 g_wvh[DD*KVD],g_wvl[DD*KVD];
__device__ __nv_bfloat16 g_woh[DD*DD], g_wol[DD*DD];

// ---------------------------------------------------------------------------
// fp32 -> (hi, lo) bf16 split. dsel: 0=x 1=wq 2=wk 3=wv 4=wo 5=V(from g_V)
// ---------------------------------------------------------------------------
__global__ void cvt_kernel(const float* srcExt, int dsel, int n)
{
    int i = blockIdx.x * blockDim.x + threadIdx.x;
    if (i >= n) return;
    const float* src = (dsel == 5) ? g_V : srcExt;
    float v = src[i];
    __nv_bfloat16 hi = __float2bfloat16(v);
    __nv_bfloat16 lo = __float2bfloat16(v - __bfloat162float(hi));
    __nv_bfloat16 *ph, *pl;
    switch (dsel) {
        case 0: ph = g_xh;  pl = g_xl;  break;
        case 1: ph = g_wqh; pl = g_wql; break;
        case 2: ph = g_wkh; pl = g_wkl; break;
        case 3: ph = g_wvh; pl = g_wvl; break;
        case 4: ph = g_woh; pl = g_wol; break;
        default:ph = g_Vh;  pl = g_Vl;  break;
    }
    ph[i] = hi; pl[i] = lo;
}

// ---------------------------------------------------------------------------
// common helpers
// ---------------------------------------------------------------------------
__device__ __forceinline__ void mma_bf16(float* c, const unsigned* a, const unsigned* b)
{
    asm volatile(
        "mma.sync.aligned.m16n8k16.row.col.f32.bf16.bf16.f32 "
        "{%0,%1,%2,%3}, {%4,%5,%6,%7}, {%8,%9}, {%0,%1,%2,%3};\n"
        : "+f"(c[0]), "+f"(c[1]), "+f"(c[2]), "+f"(c[3])
        : "r"(a[0]), "r"(a[1]), "r"(a[2]), "r"(a[3]), "r"(b[0]), "r"(b[1]));
}

__device__ __forceinline__ unsigned pack2(const __nv_bfloat16* p0, const __nv_bfloat16* p1)
{
    unsigned u0 = *(const unsigned short*)p0;
    unsigned u1 = *(const unsigned short*)p1;
    return u0 | (u1 << 16);
}

__device__ __forceinline__ unsigned pkbf(__nv_bfloat16 a, __nv_bfloat16 b)
{
    return (unsigned)__bfloat16_as_ushort(a) | ((unsigned)__bfloat16_as_ushort(b) << 16);
}

__device__ __forceinline__ void ldmx4(unsigned* r, const __nv_bfloat16* p)
{
    unsigned a = (unsigned)__cvta_generic_to_shared(p);
    asm volatile("ldmatrix.sync.aligned.m8n8.x4.shared.b16 {%0,%1,%2,%3}, [%4];"
                 : "=r"(r[0]), "=r"(r[1]), "=r"(r[2]), "=r"(r[3]) : "r"(a));
}
__device__ __forceinline__ void ldmx4t(unsigned* r, const __nv_bfloat16* p)
{
    unsigned a = (unsigned)__cvta_generic_to_shared(p);
    asm volatile("ldmatrix.sync.aligned.m8n8.x4.trans.shared.b16 {%0,%1,%2,%3}, [%4];"
                 : "=r"(r[0]), "=r"(r[1]), "=r"(r[2]), "=r"(r[3]) : "r"(a));
}

// ---------------------------------------------------------------------------
// bf16-split GEMM (unchanged from passing Round-3 kernel)
// ---------------------------------------------------------------------------
__global__ __launch_bounds__(256) void gemm_bf16split(int asel, int bsel,
                                                      float* Cext, int csel,
                                                      int M, int N, int K)
{
    const __nv_bfloat16 *Ah, *Al, *Bh, *Bl;
    if (asel == 0) { Ah = g_xh; Al = g_xl; } else { Ah = g_Ah; Al = g_Al; }
    switch (bsel) {
        case 0:  Bh = g_wqh; Bl = g_wql; break;
        case 1:  Bh = g_wkh; Bl = g_wkl; break;
        case 2:  Bh = g_wvh; Bl = g_wvl; break;
        default: Bh = g_woh; Bl = g_wol; break;
    }
    float* C = (csel == 0) ? g_Q : (csel == 1) ? g_K : (csel == 2) ? g_V : Cext;

    __shared__ __nv_bfloat16 Ash[2][128][40];
    __shared__ __nv_bfloat16 Bsh[2][32][136];

    const int tid  = threadIdx.x;
    const int lane = tid & 31;
    const int wid  = tid >> 5;
    const int g    = lane >> 2;
    const int tg   = lane & 3;
    const int warpM = (wid >> 2) * 64;
    const int warpN = (wid & 3) * 32;
    const int bm = blockIdx.y * 128;
    const int bn = blockIdx.x * 128;

    float acc[4][4][4];
#pragma unroll
    for (int a = 0; a < 4; a++)
#pragma unroll
        for (int b = 0; b < 4; b++)
#pragma unroll
            for (int c = 0; c < 4; c++) acc[a][b][c] = 0.f;

    const __nv_bfloat16* Aarr[2] = {Ah, Al};
    const __nv_bfloat16* Barr[2] = {Bh, Bl};

    uint4 pa[2][2], pb[2][2];

    auto fetch = [&](int kb) {
        const int k0 = kb * 32;
#pragma unroll
        for (int h = 0; h < 2; h++)
#pragma unroll
            for (int i = 0; i < 2; i++) {
                int q  = tid + i * 256;
                int ar = q >> 2, ak = (q & 3) * 8;
                pa[h][i] = *(const uint4*)(Aarr[h] + (size_t)(bm + ar) * K + k0 + ak);
                int bk = q >> 4, bnc = (q & 15) * 8;
                pb[h][i] = *(const uint4*)(Barr[h] + (size_t)(k0 + bk) * N + bn + bnc);
            }
    };
    auto stores = [&]() {
#pragma unroll
        for (int h = 0; h < 2; h++)
#pragma unroll
            for (int i = 0; i < 2; i++) {
                int q  = tid + i * 256;
                int ar = q >> 2, ak = (q & 3) * 8;
                *(uint2*)&Ash[h][ar][ak]     = make_uint2(pa[h][i].x, pa[h][i].y);
                *(uint2*)&Ash[h][ar][ak + 4] = make_uint2(pa[h][i].z, pa[h][i].w);
                int bk = q >> 4, bnc = (q & 15) * 8;
                *(uint4*)&Bsh[h][bk][bnc] = pb[h][i];
            }
    };

    fetch(0);
    const int nkb = K / 32;
    for (int kb = 0; kb < nkb; kb++) {
        __syncthreads();
        stores();
        if (kb + 1 < nkb) fetch(kb + 1);
        __syncthreads();

#pragma unroll
        for (int kk = 0; kk < 2; kk++) {
            const int kA = kk * 16 + tg * 2;
            unsigned ah[4][4], al2[4][4];
#pragma unroll
            for (int mt = 0; mt < 4; mt++) {
                int r0 = warpM + mt * 16 + g;
                ah[mt][0]  = *(const unsigned*)&Ash[0][r0][kA];
                ah[mt][1]  = *(const unsigned*)&Ash[0][r0 + 8][kA];
                ah[mt][2]  = *(const unsigned*)&Ash[0][r0][kA + 8];
                ah[mt][3]  = *(const unsigned*)&Ash[0][r0 + 8][kA + 8];
                al2[mt][0] = *(const unsigned*)&Ash[1][r0][kA];
                al2[mt][1] = *(const unsigned*)&Ash[1][r0 + 8][kA];
                al2[mt][2] = *(const unsigned*)&Ash[1][r0][kA + 8];
                al2[mt][3] = *(const unsigned*)&Ash[1][r0 + 8][kA + 8];
            }
            unsigned bh[4][2], bl2[4][2];
#pragma unroll
            for (int nt = 0; nt < 4; nt++) {
                int c0 = warpN + nt * 8 + g;
                bh[nt][0]  = pack2(&Bsh[0][kA][c0],     &Bsh[0][kA + 1][c0]);
                bh[nt][1]  = pack2(&Bsh[0][kA + 8][c0], &Bsh[0][kA + 9][c0]);
                bl2[nt][0] = pack2(&Bsh[1][kA][c0],     &Bsh[1][kA + 1][c0]);
                bl2[nt][1] = pack2(&Bsh[1][kA + 8][c0], &Bsh[1][kA + 9][c0]);
            }
#pragma unroll
            for (int mt = 0; mt < 4; mt++)
#pragma unroll
                for (int nt = 0; nt < 4; nt++) {
                    mma_bf16(acc[mt][nt], ah[mt],  bh[nt]);
                    mma_bf16(acc[mt][nt], ah[mt],  bl2[nt]);
                    mma_bf16(acc[mt][nt], al2[mt], bh[nt]);
                }
        }
    }

#pragma unroll
    for (int mt = 0; mt < 4; mt++)
#pragma unroll
        for (int nt = 0; nt < 4; nt++) {
            int row = bm + warpM + mt * 16 + g;
            int col = bn + warpN + nt * 8 + tg * 2;
            *(float2*)&C[(size_t)row * N + col] =
                make_float2(acc[mt][nt][0], acc[mt][nt][1]);
            *(float2*)&C[(size_t)(row + 8) * N + col] =
                make_float2(acc[mt][nt][2], acc[mt][nt][3]);
        }
}

// ---------------------------------------------------------------------------
// RoPE: read fp32 g_Q/g_K, rotate, (Q scaled by 1/8), write bf16 hi/lo splits.
// ---------------------------------------------------------------------------
__global__ void rope_split_kernel(const float* __restrict__ fcos, const float* __restrict__ fsin)
{
    const int NQP = BS * NH * (HD / 2);
    const int NKP = BS * NKV * (HD / 2);
    int idx = blockIdx.x * blockDim.x + threadIdx.x;
    if (idx < NQP) {
        int p = idx & 31;
        int srow = (idx >> 10) & (SS - 1);
        float c = fcos[srow * 32 + p];
        float sn = fsin[srow * 32 + p];
        float2 v = ((const float2*)g_Q)[idx];
        float r0 = (v.x * c - v.y * sn) * 0.125f;   // fold 1/sqrt(HD)
        float r1 = (v.x * sn + v.y * c) * 0.125f;
        __nv_bfloat16 h0 = __float2bfloat16(r0), h1 = __float2bfloat16(r1);
        __nv_bfloat16 l0 = __float2bfloat16(r0 - __bfloat162float(h0));
        __nv_bfloat16 l1 = __float2bfloat16(r1 - __bfloat162float(h1));
        ((unsigned*)g_Qh)[idx] = pkbf(h0, h1);
        ((unsigned*)g_Ql)[idx] = pkbf(l0, l1);
    } else if (idx < NQP + NKP) {
        int j = idx - NQP;
        int p = j & 31;
        int srow = (j >> 8) & (SS - 1);
        float c = fcos[srow * 32 + p];
        float sn = fsin[srow * 32 + p];
        float2 v = ((const float2*)g_K)[j];
        float r0 = v.x * c - v.y * sn;
        float r1 = v.x * sn + v.y * c;
        __nv_bfloat16 h0 = __float2bfloat16(r0), h1 = __float2bfloat16(r1);
        __nv_bfloat16 l0 = __float2bfloat16(r0 - __bfloat162float(h0));
        __nv_bfloat16 l1 = __float2bfloat16(r1 - __bfloat162float(h1));
        ((unsigned*)g_Kh)[j] = pkbf(h0, h1);
        ((unsigned*)g_Kl)[j] = pkbf(l0, l1);
    }
}

// ---------------------------------------------------------------------------
// Causal flash attention with bf16-split mma.sync.
// 64x64 tiles, 128 threads (4 warps x 16 q-rows). ldmatrix fragment feeds.
// Output written directly as bf16 hi/lo to g_Ah/g_Al.
// ---------------------------------------------------------------------------
#define ASTR 72   // smem row stride in bf16 (64 + 8 pad -> conflict-free)

__global__ __launch_bounds__(128) void attn_mma_kernel()
{
    __shared__ __nv_bfloat16 sKH[64 * ASTR], sKL[64 * ASTR];
    __shared__ __nv_bfloat16 sVH[64 * ASTR], sVL[64 * ASTR];

    const int qt = blockIdx.x;
    const int h  = blockIdx.y;
    const int b  = blockIdx.z;
    const int hk = h >> 2;
    const int tid  = threadIdx.x;
    const int lane = tid & 31;
    const int wid  = tid >> 5;          // 0..3
    const int g    = lane >> 2;
    const int tg   = lane & 3;
    const int m0   = wid * 16;
    const int q0   = qt * 64;

    // ---- stage Q (hi->sKH, lo->sKL), hoist A-fragments to registers ----
#pragma unroll
    for (int it = 0; it < 4; it++) {
        int lin = tid + it * 128;          // 0..511 (uint4 units)
        int r = lin >> 3, d8 = (lin & 7) * 8;
        size_t gb = (size_t)(b * SS + q0 + r) * DD + h * HD + d8;
        *(uint4*)&sKH[r * ASTR + d8] = *(const uint4*)(g_Qh + gb);
        *(uint4*)&sKL[r * ASTR + d8] = *(const uint4*)(g_Ql + gb);
    }
    __syncthreads();

    unsigned qh[4][4], ql[4][4];
    {
        int arow = m0 + (lane & 15);
#pragma unroll
        for (int kk = 0; kk < 4; kk++) {
            int acol = kk * 16 + (lane >> 4) * 8;
            ldmx4(qh[kk], &sKH[arow * ASTR + acol]);
            ldmx4(ql[kk], &sKL[arow * ASTR + acol]);
        }
    }
    __syncthreads();

    float oO[8][4];
#pragma unroll
    for (int i = 0; i < 8; i++)
#pragma unroll
        for (int c = 0; c < 4; c++) oO[i][c] = 0.f;
    float mrow[2] = {-1e30f, -1e30f};
    float lrow[2] = {0.f, 0.f};

    for (int kt = 0; kt <= qt; kt++) {
        // ---- load K/V tile (hi/lo) ----
#pragma unroll
        for (int it = 0; it < 4; it++) {
            int lin = tid + it * 128;
            int r = lin >> 3, d8 = (lin & 7) * 8;
            size_t gb = (size_t)(b * SS + kt * 64 + r) * KVD + hk * HD + d8;
            *(uint4*)&sKH[r * ASTR + d8] = *(const uint4*)(g_Kh + gb);
            *(uint4*)&sKL[r * ASTR + d8] = *(const uint4*)(g_Kl + gb);
            *(uint4*)&sVH[r * ASTR + d8] = *(const uint4*)(g_Vh + gb);
            *(uint4*)&sVL[r * ASTR + d8] = *(const uint4*)(g_Vl + gb);
        }
        __syncthreads();

        // ---- S = Q K^T ----
        float sS[8][4];
#pragma unroll
        for (int i = 0; i < 8; i++)
#pragma unroll
            for (int c = 0; c < 4; c++) sS[i][c] = 0.f;

        {
            int brow_base = (lane & 7) + ((lane >> 4) & 1) * 8;   // within ntile pair
            int bcol = ((lane >> 3) & 1) * 8;
#pragma unroll
            for (int kk = 0; kk < 4; kk++) {
#pragma unroll
                for (int ntp = 0; ntp < 4; ntp++) {
                    unsigned kbh[4], kbl[4];
                    const __nv_bfloat16* pb = &sKH[(ntp * 16 + brow_base) * ASTR + kk * 16 + bcol];
                    ldmx4(kbh, pb);
                    ldmx4(kbl, &sKL[(ntp * 16 + brow_base) * ASTR + kk * 16 + bcol]);
                    mma_bf16(sS[2 * ntp],     qh[kk], kbh);
                    mma_bf16(sS[2 * ntp],     qh[kk], kbl);
                    mma_bf16(sS[2 * ntp],     ql[kk], kbh);
                    mma_bf16(sS[2 * ntp + 1], qh[kk], kbh + 2);
                    mma_bf16(sS[2 * ntp + 1], qh[kk], kbl + 2);
                    mma_bf16(sS[2 * ntp + 1], ql[kk], kbh + 2);
                }
            }
        }

        // ---- causal mask (diagonal tile only) ----
        if (kt == qt) {
#pragma unroll
            for (int nt = 0; nt < 8; nt++)
#pragma unroll
                for (int c = 0; c < 4; c++) {
                    int col = nt * 8 + 2 * tg + (c & 1);
                    int row = m0 + g + ((c >> 1) & 1) * 8;
                    if (col > row) sS[nt][c] = -1e30f;
                }
        }

        // ---- online softmax (two rows per thread: g and g+8) ----
        float corr[2];
#pragma unroll
        for (int rr = 0; rr < 2; rr++) {
            float mx = -1e30f;
#pragma unroll
            for (int nt = 0; nt < 8; nt++)
                mx = fmaxf(mx, fmaxf(sS[nt][2 * rr], sS[nt][2 * rr + 1]));
            mx = fmaxf(mx, __shfl_xor_sync(0xffffffffu, mx, 1));
            mx = fmaxf(mx, __shfl_xor_sync(0xffffffffu, mx, 2));
            float mn = fmaxf(mrow[rr], mx);
            corr[rr] = __expf(mrow[rr] - mn);
            float lt = 0.f;
#pragma unroll
            for (int nt = 0; nt < 8; nt++) {
                float e0 = __expf(sS[nt][2 * rr]     - mn);
                float e1 = __expf(sS[nt][2 * rr + 1] - mn);
                sS[nt][2 * rr] = e0; sS[nt][2 * rr + 1] = e1;
                lt += e0 + e1;
            }
            lt += __shfl_xor_sync(0xffffffffu, lt, 1);
            lt += __shfl_xor_sync(0xffffffffu, lt, 2);
            lrow[rr] = lrow[rr] * corr[rr] + lt;
            mrow[rr] = mn;
        }
#pragma unroll
        for (int nt = 0; nt < 8; nt++) {
            oO[nt][0] *= corr[0]; oO[nt][1] *= corr[0];
            oO[nt][2] *= corr[1]; oO[nt][3] *= corr[1];
        }

        // ---- O += P V  (P fragments straight from registers) ----
        {
            int vrow_base = (lane & 15);
            int vcol = (lane >> 4) * 8;
#pragma unroll
            for (int kk2 = 0; kk2 < 4; kk2++) {
                unsigned aPh[4], aPl[4];
#pragma unroll
                for (int half = 0; half < 2; half++) {
                    int nt = 2 * kk2 + half;
                    __nv_bfloat16 h0 = __float2bfloat16(sS[nt][0]);
                    __nv_bfloat16 h1 = __float2bfloat16(sS[nt][1]);
                    __nv_bfloat16 h2 = __float2bfloat16(sS[nt][2]);
                    __nv_bfloat16 h3 = __float2bfloat16(sS[nt][3]);
                    aPh[2 * half]     = pkbf(h0, h1);
                    aPh[2 * half + 1] = pkbf(h2, h3);
                    __nv_bfloat16 l0 = __float2bfloat16(sS[nt][0] - __bfloat162float(h0));
                    __nv_bfloat16 l1 = __float2bfloat16(sS[nt][1] - __bfloat162float(h1));
                    __nv_bfloat16 l2 = __float2bfloat16(sS[nt][2] - __bfloat162float(h2));
                    __nv_bfloat16 l3 = __float2bfloat16(sS[nt][3] - __bfloat162float(h3));
                    aPl[2 * half]     = pkbf(l0, l1);
                    aPl[2 * half + 1] = pkbf(l2, l3);
                }
#pragma unroll
                for (int dtp = 0; dtp < 4; dtp++) {
                    unsigned vbh[4], vbl[4];
                    ldmx4t(vbh, &sVH[(kk2 * 16 + vrow_base) * ASTR + dtp * 16 + vcol]);
                    ldmx4t(vbl, &sVL[(kk2 * 16 + vrow_base) * ASTR + dtp * 16 + vcol]);
                    mma_bf16(oO[2 * dtp],     aPh, vbh);
                    mma_bf16(oO[2 * dtp],     aPh, vbl);
                    mma_bf16(oO[2 * dtp],     aPl, vbh);
                    mma_bf16(oO[2 * dtp + 1], aPh, vbh + 2);
                    mma_bf16(oO[2 * dtp + 1], aPh, vbl + 2);
                    mma_bf16(oO[2 * dtp + 1], aPl, vbh + 2);
                }
            }
        }
        __syncthreads();   // protect smem before next tile's overwrite
    }

    // ---- epilogue: normalize, split to bf16 hi/lo, store to g_Ah/g_Al ----
    float inv0 = 1.0f / lrow[0];
    float inv1 = 1.0f / lrow[1];
#pragma unroll
    for (int nt = 0; nt < 8; nt++) {
        int col = h * HD + nt * 8 + 2 * tg;
        size_t off0 = (size_t)(b * SS + q0 + m0 + g) * DD + col;
        size_t off1 = (size_t)(b * SS + q0 + m0 + g + 8) * DD + col;
        float f0 = oO[nt][0] * inv0, f1 = oO[nt][1] * inv0;
        float f2 = oO[nt][2] * inv1, f3 = oO[nt][3] * inv1;
        __nv_bfloat16 h0 = __float2bfloat16(f0), h1 = __float2bfloat16(f1);
        __nv_bfloat16 h2 = __float2bfloat16(f2), h3 = __float2bfloat16(f3);
        *(unsigned*)(g_Ah + off0) = pkbf(h0, h1);
        *(unsigned*)(g_Ah + off1) = pkbf(h2, h3);
        __nv_bfloat16 l0 = __float2bfloat16(f0 - __bfloat162float(h0));
        __nv_bfloat16 l1 = __float2bfloat16(f1 - __bfloat162float(h1));
        __nv_bfloat16 l2 = __float2bfloat16(f2 - __bfloat162float(h2));
        __nv_bfloat16 l3 = __float2bfloat16(f3 - __bfloat162float(h3));
        *(unsigned*)(g_Al + off0) = pkbf(l0, l1);
        *(unsigned*)(g_Al + off1) = pkbf(l2, l3);
    }
}

// ---------------------------------------------------------------------------
extern "C" void kernel_launch(void* const* d_in, const int* in_sizes, int n_in,
                              void* d_out, int out_size)
{
    const float* x   = (const float*)d_in[0];
    const float* fco = (const float*)d_in[1];
    const float* fsi = (const float*)d_in[2];
    const float* wq  = (const float*)d_in[3];
    const float* wk  = (const float*)d_in[4];
    const float* wv  = (const float*)d_in[5];
    const float* wo  = (const float*)d_in[6];
    float* out = (float*)d_out;

    // split-convert inputs to bf16 hi/lo
    cvt_kernel<<<(BS * DD + 255) / 256, 256>>>(x, 0, BS * DD);
    cvt_kernel<<<(DD * DD + 255) / 256, 256>>>(wq, 1, DD * DD);
    cvt_kernel<<<(DD * KVD + 255) / 256, 256>>>(wk, 2, DD * KVD);
    cvt_kernel<<<(DD * KVD + 255) / 256, 256>>>(wv, 3, DD * KVD);
    cvt_kernel<<<(DD * DD + 255) / 256, 256>>>(wo, 4, DD * DD);

    // projections (tensor core, bf16-split)
    gemm_bf16split<<<dim3(DD / 128, BS / 128), 256>>>(0, 0, nullptr, 0, BS, DD, DD);
    gemm_bf16split<<<dim3(KVD / 128, BS / 128), 256>>>(0, 1, nullptr, 1, BS, KVD, DD);
    gemm_bf16split<<<dim3(KVD / 128, BS / 128), 256>>>(0, 2, nullptr, 2, BS, KVD, DD);

    // RoPE -> bf16 splits (Q scaled by 1/8); V -> bf16 splits
    {
        int total = BS * NH * (HD / 2) + BS * NKV * (HD / 2);
        rope_split_kernel<<<(total + 255) / 256, 256>>>(fco, fsi);
    }
    cvt_kernel<<<(BS * KVD + 255) / 256, 256>>>(nullptr, 5, BS * KVD);

    // attention (tensor core)
    attn_mma_kernel<<<dim3(SS / 64, NH, BB), 128>>>();

    // output projection
    gemm_bf16split<<<dim3(DD / 128, BS / 128), 256>>>(1, 3, out, -1, BS, DD, DD);
}

// round 6
// speedup vs baseline: 5.3009x; 1.1022x over previous
#include <cuda_runtime.h>
#include <cuda_bf16.h>
#include <math.h>
#include <stdint.h>

#define BB 2
#define SS 2048
#define DD 2048
#define NH 32
#define NKV 8
#define HD 64
#define KVD (NKV*HD)   /* 512 */
#define BS (BB*SS)     /* 4096 */

// fp32 scratch (GEMM outputs)
__device__ float g_Q[BS*DD];
__device__ float g_K[BS*KVD];
__device__ float g_V[BS*KVD];

// bf16 hi/lo split scratch
__device__ __nv_bfloat16 g_xh[BS*DD],  g_xl[BS*DD];
__device__ __nv_bfloat16 g_Ah[BS*DD],  g_Al[BS*DD];
__device__ __nv_bfloat16 g_Qh[BS*DD],  g_Ql[BS*DD];
__device__ __nv_bfloat16 g_Kh[BS*KVD], g_Kl[BS*KVD];
__device__ __nv_bfloat16 g_Vh[BS*KVD], g_Vl[BS*KVD];
// transposed weight splits [N x K]
__device__ __nv_bfloat16 g_wqTh[DD*DD],  g_wqTl[DD*DD];
__device__ __nv_bfloat16 g_wkTh[KVD*DD], g_wkTl[KVD*DD];
__device__ __nv_bfloat16 g_wvTh[KVD*DD], g_wvTl[KVD*DD];
__device__ __nv_bfloat16 g_woTh[DD*DD],  g_woTl[DD*DD];

// ---------------------------------------------------------------------------
// helpers
// ---------------------------------------------------------------------------
__device__ __forceinline__ uint32_t smem_u32(const void* p) {
    uint32_t a;
    asm("{ .reg .u64 t; cvta.to.shared.u64 t, %1; cvt.u32.u64 %0, t; }"
        : "=r"(a) : "l"(p));
    return a;
}

__device__ __forceinline__ unsigned pkbf(__nv_bfloat16 a, __nv_bfloat16 b)
{
    return (unsigned)__bfloat16_as_ushort(a) | ((unsigned)__bfloat16_as_ushort(b) << 16);
}

__device__ __forceinline__ void mma_bf16(float* c, const unsigned* a, const unsigned* b)
{
    asm volatile(
        "mma.sync.aligned.m16n8k16.row.col.f32.bf16.bf16.f32 "
        "{%0,%1,%2,%3}, {%4,%5,%6,%7}, {%8,%9}, {%0,%1,%2,%3};\n"
        : "+f"(c[0]), "+f"(c[1]), "+f"(c[2]), "+f"(c[3])
        : "r"(a[0]), "r"(a[1]), "r"(a[2]), "r"(a[3]), "r"(b[0]), "r"(b[1]));
}

__device__ __forceinline__ void ldmx4(unsigned* r, const __nv_bfloat16* p)
{
    unsigned a = smem_u32(p);
    asm volatile("ldmatrix.sync.aligned.m8n8.x4.shared.b16 {%0,%1,%2,%3}, [%4];"
                 : "=r"(r[0]), "=r"(r[1]), "=r"(r[2]), "=r"(r[3]) : "r"(a));
}
__device__ __forceinline__ void ldmx4t(unsigned* r, const __nv_bfloat16* p)
{
    unsigned a = smem_u32(p);
    asm volatile("ldmatrix.sync.aligned.m8n8.x4.trans.shared.b16 {%0,%1,%2,%3}, [%4];"
                 : "=r"(r[0]), "=r"(r[1]), "=r"(r[2]), "=r"(r[3]) : "r"(a));
}

// ---------------------------------------------------------------------------
// fp32 -> (hi, lo) bf16 split. dsel: 0 = x -> g_xh/g_xl, 1 = g_V -> g_Vh/g_Vl
// ---------------------------------------------------------------------------
__global__ void cvt_kernel(const float* srcExt, int dsel, int n)
{
    int i = blockIdx.x * blockDim.x + threadIdx.x;
    if (i >= n) return;
    const float* src = (dsel == 1) ? g_V : srcExt;
    float v = src[i];
    __nv_bfloat16 hi = __float2bfloat16(v);
    __nv_bfloat16 lo = __float2bfloat16(v - __bfloat162float(hi));
    __nv_bfloat16* ph = (dsel == 1) ? g_Vh : g_xh;
    __nv_bfloat16* pl = (dsel == 1) ? g_Vl : g_xl;
    ph[i] = hi; pl[i] = lo;
}

// ---------------------------------------------------------------------------
// Weight transpose + split: w [K,N] fp32 -> wT hi/lo [N,K] bf16.
// ---------------------------------------------------------------------------
__global__ void wtr_kernel(const float* __restrict__ w, int dsel, int K, int N)
{
    __shared__ float t[32][33];
    __nv_bfloat16 *ph, *pl;
    switch (dsel) {
        case 0: ph = g_wqTh; pl = g_wqTl; break;
        case 1: ph = g_wkTh; pl = g_wkTl; break;
        case 2: ph = g_wvTh; pl = g_wvTl; break;
        default:ph = g_woTh; pl = g_woTl; break;
    }
    int n0 = blockIdx.x * 32, k0 = blockIdx.y * 32;
    int tx = threadIdx.x, ty = threadIdx.y;
#pragma unroll
    for (int yy = 0; yy < 4; yy++) {
        int k = k0 + ty + yy * 8;
        t[ty + yy * 8][tx] = w[(size_t)k * N + n0 + tx];
    }
    __syncthreads();
#pragma unroll
    for (int yy = 0; yy < 4; yy++) {
        int n = n0 + ty + yy * 8;
        float v = t[tx][ty + yy * 8];
        __nv_bfloat16 hi = __float2bfloat16(v);
        __nv_bfloat16 lo = __float2bfloat16(v - __bfloat162float(hi));
        ph[(size_t)n * K + k0 + tx] = hi;
        pl[(size_t)n * K + k0 + tx] = lo;
    }
}

// ---------------------------------------------------------------------------
// bf16-split GEMM on mma.sync with ldmatrix fragments + cp.async pipeline.
// C[M,N] = A[M,K] @ B^T, B stored [N,K].  128x128 tile, BK=32, 256 threads.
// 8 warps: warpM = (wid>>2)*64, warpN = (wid&3)*32.
// Dynamic smem: 2 stages x 4 matrices x [128][40] bf16 = 81920 B.
// ---------------------------------------------------------------------------
#define GSTR 40                       /* padded row stride (bf16 elems) */
#define GMAT (128*GSTR*2)             /* bytes per matrix buffer: 10240 */
#define GSTAGE (4*GMAT)               /* 40960 */
#define GEMM_SMEM (2*GSTAGE)          /* 81920 */

__global__ __launch_bounds__(256) void gemm_mma(int asel, int bsel,
                                                float* Cext, int csel,
                                                int M, int N, int K)
{
    extern __shared__ char dsm[];

    const __nv_bfloat16* Ah = asel ? g_Ah : g_xh;
    const __nv_bfloat16* Al = asel ? g_Al : g_xl;
    const __nv_bfloat16 *Bh, *Bl;
    switch (bsel) {
        case 0:  Bh = g_wqTh; Bl = g_wqTl; break;
        case 1:  Bh = g_wkTh; Bl = g_wkTl; break;
        case 2:  Bh = g_wvTh; Bl = g_wvTl; break;
        default: Bh = g_woTh; Bl = g_woTl; break;
    }
    float* C = (csel == 0) ? g_Q : (csel == 1) ? g_K : (csel == 2) ? g_V : Cext;

    const int tid  = threadIdx.x;
    const int lane = tid & 31;
    const int wid  = tid >> 5;
    const int g    = lane >> 2;
    const int tg   = lane & 3;
    const int warpM = (wid >> 2) * 64;
    const int warpN = (wid & 3) * 32;
    const int bm = blockIdx.y * 128;
    const int bn = blockIdx.x * 128;

    const __nv_bfloat16* srcs[4] = {Ah, Al, Bh, Bl};

    float acc[4][4][4];
#pragma unroll
    for (int a = 0; a < 4; a++)
#pragma unroll
        for (int b = 0; b < 4; b++)
#pragma unroll
            for (int c = 0; c < 4; c++) acc[a][b][c] = 0.f;

    // cp.async copy of K-chunk ch into stage ch&1
    auto docopy = [&](int ch) {
        const uint32_t sb = smem_u32(dsm) + (ch & 1) * GSTAGE;
#pragma unroll
        for (int it = 0; it < 8; it++) {
            int o = tid + it * 256;
            int mat = o >> 9;
            int idx = o & 511;
            int r = idx >> 2, c8 = (idx & 3) * 8;
            int rowbase = (mat < 2) ? bm : bn;
            uint32_t so = sb + mat * GMAT + r * (GSTR * 2) + c8 * 2;
            const __nv_bfloat16* gp = srcs[mat] + (size_t)(rowbase + r) * K + ch * 32 + c8;
            asm volatile("cp.async.cg.shared.global [%0], [%1], 16;\n"
                         :: "r"(so), "l"(gp));
        }
        asm volatile("cp.async.commit_group;\n");
    };

    const int nkb = K / 32;
    docopy(0);

    for (int kb = 0; kb < nkb; kb++) {
        if (kb + 1 < nkb) {
            docopy(kb + 1);
            asm volatile("cp.async.wait_group 1;\n" ::: "memory");
        } else {
            asm volatile("cp.async.wait_group 0;\n" ::: "memory");
        }
        __syncthreads();

        const __nv_bfloat16* sAh = (const __nv_bfloat16*)(dsm + (kb & 1) * GSTAGE);
        const __nv_bfloat16* sAl = sAh + 128 * GSTR;
        const __nv_bfloat16* sBh = sAl + 128 * GSTR;
        const __nv_bfloat16* sBl = sBh + 128 * GSTR;

#pragma unroll
        for (int ks = 0; ks < 2; ks++) {
            const int kc = ks * 16;
            // A fragments (16x16 per mtile), hi + lo
            unsigned ah[4][4], al[4][4];
            {
                int arow = warpM + (lane & 15);
                int acol = kc + (lane >> 4) * 8;
#pragma unroll
                for (int mt = 0; mt < 4; mt++) {
                    ldmx4(ah[mt], &sAh[(arow + mt * 16) * GSTR + acol]);
                    ldmx4(al[mt], &sAl[(arow + mt * 16) * GSTR + acol]);
                }
            }
            // B fragments (16n x 16k per group), hi + lo
            unsigned bh[2][4], bl[2][4];
            {
                int brow = (lane & 7) + ((lane >> 4) & 1) * 8;
                int bcol = kc + ((lane >> 3) & 1) * 8;
#pragma unroll
                for (int ng = 0; ng < 2; ng++) {
                    ldmx4(bh[ng], &sBh[(warpN + ng * 16 + brow) * GSTR + bcol]);
                    ldmx4(bl[ng], &sBl[(warpN + ng * 16 + brow) * GSTR + bcol]);
                }
            }
#pragma unroll
            for (int mt = 0; mt < 4; mt++)
#pragma unroll
                for (int ng = 0; ng < 2; ng++) {
                    mma_bf16(acc[mt][2 * ng],     ah[mt], bh[ng]);
                    mma_bf16(acc[mt][2 * ng],     ah[mt], bl[ng]);
                    mma_bf16(acc[mt][2 * ng],     al[mt], bh[ng]);
                    mma_bf16(acc[mt][2 * ng + 1], ah[mt], bh[ng] + 2);
                    mma_bf16(acc[mt][2 * ng + 1], ah[mt], bl[ng] + 2);
                    mma_bf16(acc[mt][2 * ng + 1], al[mt], bh[ng] + 2);
                }
        }
        __syncthreads();
    }

#pragma unroll
    for (int mt = 0; mt < 4; mt++)
#pragma unroll
        for (int nt = 0; nt < 4; nt++) {
            int row = bm + warpM + mt * 16 + g;
            int col = bn + warpN + nt * 8 + tg * 2;
            *(float2*)&C[(size_t)row * N + col] =
                make_float2(acc[mt][nt][0], acc[mt][nt][1]);
            *(float2*)&C[(size_t)(row + 8) * N + col] =
                make_float2(acc[mt][nt][2], acc[mt][nt][3]);
        }
}

// ---------------------------------------------------------------------------
// RoPE: read fp32 g_Q/g_K, rotate, (Q scaled by 1/8), write bf16 hi/lo splits.
// ---------------------------------------------------------------------------
__global__ void rope_split_kernel(const float* __restrict__ fcos, const float* __restrict__ fsin)
{
    const int NQP = BS * NH * (HD / 2);
    const int NKP = BS * NKV * (HD / 2);
    int idx = blockIdx.x * blockDim.x + threadIdx.x;
    if (idx < NQP) {
        int p = idx & 31;
        int srow = (idx >> 10) & (SS - 1);
        float c = fcos[srow * 32 + p];
        float sn = fsin[srow * 32 + p];
        float2 v = ((const float2*)g_Q)[idx];
        float r0 = (v.x * c - v.y * sn) * 0.125f;
        float r1 = (v.x * sn + v.y * c) * 0.125f;
        __nv_bfloat16 h0 = __float2bfloat16(r0), h1 = __float2bfloat16(r1);
        __nv_bfloat16 l0 = __float2bfloat16(r0 - __bfloat162float(h0));
        __nv_bfloat16 l1 = __float2bfloat16(r1 - __bfloat162float(h1));
        ((unsigned*)g_Qh)[idx] = pkbf(h0, h1);
        ((unsigned*)g_Ql)[idx] = pkbf(l0, l1);
    } else if (idx < NQP + NKP) {
        int j = idx - NQP;
        int p = j & 31;
        int srow = (j >> 8) & (SS - 1);
        float c = fcos[srow * 32 + p];
        float sn = fsin[srow * 32 + p];
        float2 v = ((const float2*)g_K)[j];
        float r0 = v.x * c - v.y * sn;
        float r1 = v.x * sn + v.y * c;
        __nv_bfloat16 h0 = __float2bfloat16(r0), h1 = __float2bfloat16(r1);
        __nv_bfloat16 l0 = __float2bfloat16(r0 - __bfloat162float(h0));
        __nv_bfloat16 l1 = __float2bfloat16(r1 - __bfloat162float(h1));
        ((unsigned*)g_Kh)[j] = pkbf(h0, h1);
        ((unsigned*)g_Kl)[j] = pkbf(l0, l1);
    }
}

// ---------------------------------------------------------------------------
// Causal flash attention with bf16-split mma.sync (unchanged from Round 4).
// ---------------------------------------------------------------------------
#define ASTR 72

__global__ __launch_bounds__(128) void attn_mma_kernel()
{
    __shared__ __nv_bfloat16 sKH[64 * ASTR], sKL[64 * ASTR];
    __shared__ __nv_bfloat16 sVH[64 * ASTR], sVL[64 * ASTR];

    const int qt = blockIdx.x;
    const int h  = blockIdx.y;
    const int b  = blockIdx.z;
    const int hk = h >> 2;
    const int tid  = threadIdx.x;
    const int lane = tid & 31;
    const int wid  = tid >> 5;
    const int g    = lane >> 2;
    const int tg   = lane & 3;
    const int m0   = wid * 16;
    const int q0   = qt * 64;

#pragma unroll
    for (int it = 0; it < 4; it++) {
        int lin = tid + it * 128;
        int r = lin >> 3, d8 = (lin & 7) * 8;
        size_t gb = (size_t)(b * SS + q0 + r) * DD + h * HD + d8;
        *(uint4*)&sKH[r * ASTR + d8] = *(const uint4*)(g_Qh + gb);
        *(uint4*)&sKL[r * ASTR + d8] = *(const uint4*)(g_Ql + gb);
    }
    __syncthreads();

    unsigned qh[4][4], ql[4][4];
    {
        int arow = m0 + (lane & 15);
#pragma unroll
        for (int kk = 0; kk < 4; kk++) {
            int acol = kk * 16 + (lane >> 4) * 8;
            ldmx4(qh[kk], &sKH[arow * ASTR + acol]);
            ldmx4(ql[kk], &sKL[arow * ASTR + acol]);
        }
    }
    __syncthreads();

    float oO[8][4];
#pragma unroll
    for (int i = 0; i < 8; i++)
#pragma unroll
        for (int c = 0; c < 4; c++) oO[i][c] = 0.f;
    float mrow[2] = {-1e30f, -1e30f};
    float lrow[2] = {0.f, 0.f};

    for (int kt = 0; kt <= qt; kt++) {
#pragma unroll
        for (int it = 0; it < 4; it++) {
            int lin = tid + it * 128;
            int r = lin >> 3, d8 = (lin & 7) * 8;
            size_t gb = (size_t)(b * SS + kt * 64 + r) * KVD + hk * HD + d8;
            *(uint4*)&sKH[r * ASTR + d8] = *(const uint4*)(g_Kh + gb);
            *(uint4*)&sKL[r * ASTR + d8] = *(const uint4*)(g_Kl + gb);
            *(uint4*)&sVH[r * ASTR + d8] = *(const uint4*)(g_Vh + gb);
            *(uint4*)&sVL[r * ASTR + d8] = *(const uint4*)(g_Vl + gb);
        }
        __syncthreads();

        float sS[8][4];
#pragma unroll
        for (int i = 0; i < 8; i++)
#pragma unroll
            for (int c = 0; c < 4; c++) sS[i][c] = 0.f;

        {
            int brow_base = (lane & 7) + ((lane >> 4) & 1) * 8;
            int bcol = ((lane >> 3) & 1) * 8;
#pragma unroll
            for (int kk = 0; kk < 4; kk++) {
#pragma unroll
                for (int ntp = 0; ntp < 4; ntp++) {
                    unsigned kbh[4], kbl[4];
                    ldmx4(kbh, &sKH[(ntp * 16 + brow_base) * ASTR + kk * 16 + bcol]);
                    ldmx4(kbl, &sKL[(ntp * 16 + brow_base) * ASTR + kk * 16 + bcol]);
                    mma_bf16(sS[2 * ntp],     qh[kk], kbh);
                    mma_bf16(sS[2 * ntp],     qh[kk], kbl);
                    mma_bf16(sS[2 * ntp],     ql[kk], kbh);
                    mma_bf16(sS[2 * ntp + 1], qh[kk], kbh + 2);
                    mma_bf16(sS[2 * ntp + 1], qh[kk], kbl + 2);
                    mma_bf16(sS[2 * ntp + 1], ql[kk], kbh + 2);
                }
            }
        }

        if (kt == qt) {
#pragma unroll
            for (int nt = 0; nt < 8; nt++)
#pragma unroll
                for (int c = 0; c < 4; c++) {
                    int col = nt * 8 + 2 * tg + (c & 1);
                    int row = m0 + g + ((c >> 1) & 1) * 8;
                    if (col > row) sS[nt][c] = -1e30f;
                }
        }

        float corr[2];
#pragma unroll
        for (int rr = 0; rr < 2; rr++) {
            float mx = -1e30f;
#pragma unroll
            for (int nt = 0; nt < 8; nt++)
                mx = fmaxf(mx, fmaxf(sS[nt][2 * rr], sS[nt][2 * rr + 1]));
            mx = fmaxf(mx, __shfl_xor_sync(0xffffffffu, mx, 1));
            mx = fmaxf(mx, __shfl_xor_sync(0xffffffffu, mx, 2));
            float mn = fmaxf(mrow[rr], mx);
            corr[rr] = __expf(mrow[rr] - mn);
            float lt = 0.f;
#pragma unroll
            for (int nt = 0; nt < 8; nt++) {
                float e0 = __expf(sS[nt][2 * rr]     - mn);
                float e1 = __expf(sS[nt][2 * rr + 1] - mn);
                sS[nt][2 * rr] = e0; sS[nt][2 * rr + 1] = e1;
                lt += e0 + e1;
            }
            lt += __shfl_xor_sync(0xffffffffu, lt, 1);
            lt += __shfl_xor_sync(0xffffffffu, lt, 2);
            lrow[rr] = lrow[rr] * corr[rr] + lt;
            mrow[rr] = mn;
        }
#pragma unroll
        for (int nt = 0; nt < 8; nt++) {
            oO[nt][0] *= corr[0]; oO[nt][1] *= corr[0];
            oO[nt][2] *= corr[1]; oO[nt][3] *= corr[1];
        }

        {
            int vrow_base = (lane & 15);
            int vcol = (lane >> 4) * 8;
#pragma unroll
            for (int kk2 = 0; kk2 < 4; kk2++) {
                unsigned aPh[4], aPl[4];
#pragma unroll
                for (int half = 0; half < 2; half++) {
                    int nt = 2 * kk2 + half;
                    __nv_bfloat16 h0 = __float2bfloat16(sS[nt][0]);
                    __nv_bfloat16 h1 = __float2bfloat16(sS[nt][1]);
                    __nv_bfloat16 h2 = __float2bfloat16(sS[nt][2]);
                    __nv_bfloat16 h3 = __float2bfloat16(sS[nt][3]);
                    aPh[2 * half]     = pkbf(h0, h1);
                    aPh[2 * half + 1] = pkbf(h2, h3);
                    __nv_bfloat16 l0 = __float2bfloat16(sS[nt][0] - __bfloat162float(h0));
                    __nv_bfloat16 l1 = __float2bfloat16(sS[nt][1] - __bfloat162float(h1));
                    __nv_bfloat16 l2 = __float2bfloat16(sS[nt][2] - __bfloat162float(h2));
                    __nv_bfloat16 l3 = __float2bfloat16(sS[nt][3] - __bfloat162float(h3));
                    aPl[2 * half]     = pkbf(l0, l1);
                    aPl[2 * half + 1] = pkbf(l2, l3);
                }
#pragma unroll
                for (int dtp = 0; dtp < 4; dtp++) {
                    unsigned vbh[4], vbl[4];
                    ldmx4t(vbh, &sVH[(kk2 * 16 + vrow_base) * ASTR + dtp * 16 + vcol]);
                    ldmx4t(vbl, &sVL[(kk2 * 16 + vrow_base) * ASTR + dtp * 16 + vcol]);
                    mma_bf16(oO[2 * dtp],     aPh, vbh);
                    mma_bf16(oO[2 * dtp],     aPh, vbl);
                    mma_bf16(oO[2 * dtp],     aPl, vbh);
                    mma_bf16(oO[2 * dtp + 1], aPh, vbh + 2);
                    mma_bf16(oO[2 * dtp + 1], aPh, vbl + 2);
                    mma_bf16(oO[2 * dtp + 1], aPl, vbh + 2);
                }
            }
        }
        __syncthreads();
    }

    float inv0 = 1.0f / lrow[0];
    float inv1 = 1.0f / lrow[1];
#pragma unroll
    for (int nt = 0; nt < 8; nt++) {
        int col = h * HD + nt * 8 + 2 * tg;
        size_t off0 = (size_t)(b * SS + q0 + m0 + g) * DD + col;
        size_t off1 = (size_t)(b * SS + q0 + m0 + g + 8) * DD + col;
        float f0 = oO[nt][0] * inv0, f1 = oO[nt][1] * inv0;
        float f2 = oO[nt][2] * inv1, f3 = oO[nt][3] * inv1;
        __nv_bfloat16 h0 = __float2bfloat16(f0), h1 = __float2bfloat16(f1);
        __nv_bfloat16 h2 = __float2bfloat16(f2), h3 = __float2bfloat16(f3);
        *(unsigned*)(g_Ah + off0) = pkbf(h0, h1);
        *(unsigned*)(g_Ah + off1) = pkbf(h2, h3);
        __nv_bfloat16 l0 = __float2bfloat16(f0 - __bfloat162float(h0));
        __nv_bfloat16 l1 = __float2bfloat16(f1 - __bfloat162float(h1));
        __nv_bfloat16 l2 = __float2bfloat16(f2 - __bfloat162float(h2));
        __nv_bfloat16 l3 = __float2bfloat16(f3 - __bfloat162float(h3));
        *(unsigned*)(g_Al + off0) = pkbf(l0, l1);
        *(unsigned*)(g_Al + off1) = pkbf(l2, l3);
    }
}

// ---------------------------------------------------------------------------
extern "C" void kernel_launch(void* const* d_in, const int* in_sizes, int n_in,
                              void* d_out, int out_size)
{
    const float* x   = (const float*)d_in[0];
    const float* fco = (const float*)d_in[1];
    const float* fsi = (const float*)d_in[2];
    const float* wq  = (const float*)d_in[3];
    const float* wk  = (const float*)d_in[4];
    const float* wv  = (const float*)d_in[5];
    const float* wo  = (const float*)d_in[6];
    float* out = (float*)d_out;

    cudaFuncSetAttribute(gemm_mma, cudaFuncAttributeMaxDynamicSharedMemorySize, GEMM_SMEM);

    // split x; transpose+split weights
    cvt_kernel<<<(BS * DD + 255) / 256, 256>>>(x, 0, BS * DD);
    wtr_kernel<<<dim3(DD / 32, DD / 32), dim3(32, 8)>>>(wq, 0, DD, DD);
    wtr_kernel<<<dim3(KVD / 32, DD / 32), dim3(32, 8)>>>(wk, 1, DD, KVD);
    wtr_kernel<<<dim3(KVD / 32, DD / 32), dim3(32, 8)>>>(wv, 2, DD, KVD);
    wtr_kernel<<<dim3(DD / 32, DD / 32), dim3(32, 8)>>>(wo, 3, DD, DD);

    // projections (mma.sync + cp.async pipeline)
    gemm_mma<<<dim3(DD / 128, BS / 128), 256, GEMM_SMEM>>>(0, 0, nullptr, 0, BS, DD, DD);
    gemm_mma<<<dim3(KVD / 128, BS / 128), 256, GEMM_SMEM>>>(0, 1, nullptr, 1, BS, KVD, DD);
    gemm_mma<<<dim3(KVD / 128, BS / 128), 256, GEMM_SMEM>>>(0, 2, nullptr, 2, BS, KVD, DD);

    // RoPE -> bf16 splits (Q scaled by 1/8); V -> bf16 splits
    {
        int total = BS * NH * (HD / 2) + BS * NKV * (HD / 2);
        rope_split_kernel<<<(total + 255) / 256, 256>>>(fco, fsi);
    }
    cvt_kernel<<<(BS * KVD + 255) / 256, 256>>>(nullptr, 1, BS * KVD);

    // attention (mma.sync tensor path)
    attn_mma_kernel<<<dim3(SS / 64, NH, BB), 128>>>();

    // output projection
    gemm_mma<<<dim3(DD / 128, BS / 128), 256, GEMM_SMEM>>>(1, 3, out, -1, BS, DD, DD);
}